// round 7
// baseline (speedup 1.0000x reference)
#include <cuda_runtime.h>
#include <math.h>

// Problem constants
#define BB 32
#define NN 128
#define FF 128
#define GG 300
#define NPAIR (BB*NN*NN)     // 524288 pairs
#define NROW  (BB*NN)        // 4096 atom rows
#define KC 12                // rbf K-chunk (300 = 25*12)
#define NCHUNK 25
#define NTILE 16             // 128/8 row-tiles per batch
#define NTRI  (NTILE*(NTILE+1)/2)   // 136 upper-triangle tile pairs
#define LOG2F_ 0.69314718055994530942f

typedef unsigned long long u64;

// Scratch: device globals (no runtime allocation allowed)
// g_W holds only rows (i,j) with (i>>3) <= (j>>3)  (tile-level upper triangle;
// diagonal 8x8 tiles hold all 64 pairs). W[b,i,j,:] == W[b,j,i,:] by symmetry.
static __device__ float g_W[(size_t)NPAIR * FF];  // 256 MiB filter matrix
static __device__ float g_x[NROW * FF];
static __device__ float g_f[NROW * FF];
static __device__ float g_y[NROW * FF];

// ---------------- packed f32x2 helpers (Blackwell FFMA2) ----------------
__device__ __forceinline__ u64 pack2(float lo, float hi) {
    u64 r;
    asm("mov.b64 %0, {%1, %2};" : "=l"(r) : "f"(lo), "f"(hi));
    return r;
}
__device__ __forceinline__ void unpack2(u64 v, float& lo, float& hi) {
    asm("mov.b64 {%0, %1}, %2;" : "=f"(lo), "=f"(hi) : "l"(v));
}
__device__ __forceinline__ u64 ffma2(u64 a, u64 b, u64 c) {
    u64 d;
    asm("fma.rn.f32x2 %0, %1, %2, %3;" : "=l"(d) : "l"(a), "l"(b), "l"(c));
    return d;
}

// shifted softplus: log(0.5*exp(x)+0.5) == softplus(x) - log(2)
__device__ __forceinline__ float sspf(float x) {
    if (x > 30.0f) return x - LOG2F_;
    return __logf(fmaf(0.5f, __expf(x), 0.5f));
}

__device__ __forceinline__ void fma_row(float acc[8], float a, float4 w0, float4 w1) {
    acc[0] = fmaf(a, w0.x, acc[0]); acc[1] = fmaf(a, w0.y, acc[1]);
    acc[2] = fmaf(a, w0.z, acc[2]); acc[3] = fmaf(a, w0.w, acc[3]);
    acc[4] = fmaf(a, w1.x, acc[4]); acc[5] = fmaf(a, w1.y, acc[5]);
    acc[6] = fmaf(a, w1.z, acc[6]); acc[7] = fmaf(a, w1.w, acc[7]);
}

// ------------------------------------------------------------------
// Embedding gather: x[b,n,:] = emb[z[b,n], :]
// ------------------------------------------------------------------
__global__ void embed_kernel(const int* __restrict__ z, const float* __restrict__ emb) {
    int idx = blockIdx.x * blockDim.x + threadIdx.x;  // exactly NROW*FF threads
    int row = idx >> 7;
    int f   = idx & 127;
    g_x[idx] = emb[(z[row] << 7) + f];
}

// ------------------------------------------------------------------
// Filter: W[p,:] = (ssp(rbf(d_p) @ w_f1 + b_f1)) @ w_f2 + b_f2
// SYMMETRY: compute only upper-triangle 8x8 tile-pairs (ti <= tj);
// store ONLY the computed tile (consumers read (min,max)).
// CTA = 64 pairs (8 i-rows x 8 j-cols) x 128 features, 128 threads.
// Thread (tx = tid&15, ty = tid>>4) owns pairs {8ty..8ty+7} and
// features {4tx..4tx+3} U {64+4tx..64+4tx+3}  (conflict-free LDS phases).
// ------------------------------------------------------------------
__global__ __launch_bounds__(128, 2) void filter_kernel(
    const float* __restrict__ r,
    const float* __restrict__ wf1, const float* __restrict__ bf1,
    const float* __restrict__ wf2, const float* __restrict__ bf2)
{
    __shared__ float h1_s[64 * 132];      // [pair][feat], stride 132 (528B, 16B-mult)
    __shared__ float wf1_s[KC * 128];
    __shared__ float rbf_s[KC * 64];
    __shared__ float d_s[64];

    const int tid = threadIdx.x;
    const int tx = tid & 15;
    const int ty = tid >> 4;              // 0..7
    const int fA = tx << 2;               // first feature group base
    const int fB = 64 + (tx << 2);        // second feature group base

    // decode blockIdx -> (batch, upper-triangle tile pair)
    const int b = blockIdx.x / NTRI;
    int t = blockIdx.x - b * NTRI;
    int ti = 0;
    while (t >= NTILE - ti) { t -= NTILE - ti; ti++; }
    const int tj = ti + t;
    const int i0 = ti << 3;               // 8 i-rows
    const int j0 = tj << 3;               // 8 j-cols

    // pairwise distances: local pair q -> (i0 + (q>>3), j0 + (q&7))
    if (tid < 64) {
        int i = i0 + (tid >> 3), j = j0 + (tid & 7);
        const float* ri = r + (b * NN + i) * 3;
        const float* rj = r + (b * NN + j) * 3;
        float dx = ri[0] - rj[0], dy = ri[1] - rj[1], dz = ri[2] - rj[2];
        d_s[tid] = sqrtf(dx * dx + dy * dy + dz * dz + 1e-12f);
    }

    // phase-1 accumulators (init with b_f1)
    u64 acc[8][4];
    {
        u64 b0 = pack2(__ldg(&bf1[fA]),     __ldg(&bf1[fA + 1]));
        u64 b1 = pack2(__ldg(&bf1[fA + 2]), __ldg(&bf1[fA + 3]));
        u64 b2 = pack2(__ldg(&bf1[fB]),     __ldg(&bf1[fB + 1]));
        u64 b3 = pack2(__ldg(&bf1[fB + 2]), __ldg(&bf1[fB + 3]));
#pragma unroll
        for (int p = 0; p < 8; p++) { acc[p][0]=b0; acc[p][1]=b1; acc[p][2]=b2; acc[p][3]=b3; }
    }
    __syncthreads();

    const float step = 30.0f / 299.0f;
    for (int c = 0; c < NCHUNK; c++) {
        const int g0 = c * KC;
        // stage w_f1 chunk: KC*128 floats = 384 float4 (3 iters)
        {
            const float4* src = (const float4*)(wf1 + g0 * FF);
            float4* dst = (float4*)wf1_s;
#pragma unroll
            for (int i = 0; i < 3; i++) dst[tid + i * 128] = __ldg(&src[tid + i * 128]);
        }
        // generate rbf chunk: exp(-10*(d - c_g)^2)   (768 elems, 6 iters)
#pragma unroll
        for (int i = 0; i < 6; i++) {
            int lin = tid + i * 128;
            int k = lin >> 6, p = lin & 63;
            float dd = d_s[p] - (float)(g0 + k) * step;
            rbf_s[lin] = __expf(-10.0f * dd * dd);
        }
        __syncthreads();
#pragma unroll
        for (int k = 0; k < KC; k++) {
            float4 w0 = *(const float4*)&wf1_s[(k << 7) + fA];
            float4 w1 = *(const float4*)&wf1_s[(k << 7) + fB];
            u64 pw0 = pack2(w0.x, w0.y), pw1 = pack2(w0.z, w0.w);
            u64 pw2 = pack2(w1.x, w1.y), pw3 = pack2(w1.z, w1.w);
            float4 aL = *(const float4*)&rbf_s[(k << 6) + (ty << 3)];
            float4 aH = *(const float4*)&rbf_s[(k << 6) + (ty << 3) + 4];
            float av[8] = {aL.x, aL.y, aL.z, aL.w, aH.x, aH.y, aH.z, aH.w};
#pragma unroll
            for (int p = 0; p < 8; p++) {
                u64 pa = pack2(av[p], av[p]);
                acc[p][0] = ffma2(pw0, pa, acc[p][0]);
                acc[p][1] = ffma2(pw1, pa, acc[p][1]);
                acc[p][2] = ffma2(pw2, pa, acc[p][2]);
                acc[p][3] = ffma2(pw3, pa, acc[p][3]);
            }
        }
        __syncthreads();
    }

    // ssp, write h1 pair-major into smem (conflict-free: banks tx*4..)
#pragma unroll
    for (int p = 0; p < 8; p++) {
        float v[8];
        unpack2(acc[p][0], v[0], v[1]);
        unpack2(acc[p][1], v[2], v[3]);
        unpack2(acc[p][2], v[4], v[5]);
        unpack2(acc[p][3], v[6], v[7]);
        float* row = &h1_s[((ty << 3) + p) * 132];
        *(float4*)&row[fA] = make_float4(sspf(v[0]), sspf(v[1]), sspf(v[2]), sspf(v[3]));
        *(float4*)&row[fB] = make_float4(sspf(v[4]), sspf(v[5]), sspf(v[6]), sspf(v[7]));
    }
    __syncthreads();

    // phase 2: h1 @ w_f2 + b_f2  (k vectorized by 4; w_f2 from L1)
    u64 acc2[8][4];
    {
        u64 b0 = pack2(__ldg(&bf2[fA]),     __ldg(&bf2[fA + 1]));
        u64 b1 = pack2(__ldg(&bf2[fA + 2]), __ldg(&bf2[fA + 3]));
        u64 b2 = pack2(__ldg(&bf2[fB]),     __ldg(&bf2[fB + 1]));
        u64 b3 = pack2(__ldg(&bf2[fB + 2]), __ldg(&bf2[fB + 3]));
#pragma unroll
        for (int p = 0; p < 8; p++) { acc2[p][0]=b0; acc2[p][1]=b1; acc2[p][2]=b2; acc2[p][3]=b3; }
    }

    for (int k0 = 0; k0 < FF; k0 += 4) {
        // w block: 4 k-values x 8 features
        u64 pw[4][4];
#pragma unroll
        for (int kk = 0; kk < 4; kk++) {
            float4 wA = __ldg((const float4*)&wf2[((k0 + kk) << 7) + fA]);
            float4 wB = __ldg((const float4*)&wf2[((k0 + kk) << 7) + fB]);
            pw[kk][0] = pack2(wA.x, wA.y); pw[kk][1] = pack2(wA.z, wA.w);
            pw[kk][2] = pack2(wB.x, wB.y); pw[kk][3] = pack2(wB.z, wB.w);
        }
#pragma unroll
        for (int p = 0; p < 8; p++) {
            float4 a4 = *(const float4*)&h1_s[((ty << 3) + p) * 132 + k0];
            float av[4] = {a4.x, a4.y, a4.z, a4.w};
#pragma unroll
            for (int kk = 0; kk < 4; kk++) {
                u64 pa = pack2(av[kk], av[kk]);
                acc2[p][0] = ffma2(pw[kk][0], pa, acc2[p][0]);
                acc2[p][1] = ffma2(pw[kk][1], pa, acc2[p][1]);
                acc2[p][2] = ffma2(pw[kk][2], pa, acc2[p][2]);
                acc2[p][3] = ffma2(pw[kk][3], pa, acc2[p][3]);
            }
        }
    }

    // store W tile (triangle only — consumers read (min,max))
#pragma unroll
    for (int p = 0; p < 8; p++) {
        float v[8];
        unpack2(acc2[p][0], v[0], v[1]);
        unpack2(acc2[p][1], v[2], v[3]);
        unpack2(acc2[p][2], v[4], v[5]);
        unpack2(acc2[p][3], v[6], v[7]);
        int q = (ty << 3) + p;            // local pair index
        int i = i0 + (q >> 3), j = j0 + (q & 7);
        size_t row1 = (size_t)((b * NN + i) * NN + j);
        *(float4*)(g_W + row1 * FF + fA) = make_float4(v[0], v[1], v[2], v[3]);
        *(float4*)(g_W + row1 * FF + fB) = make_float4(v[4], v[5], v[6], v[7]);
    }
}

// ------------------------------------------------------------------
// f = x @ w_in2f  (no bias). 32 rows per CTA.
// ------------------------------------------------------------------
__global__ __launch_bounds__(256) void f_kernel(const float* __restrict__ w)
{
    __shared__ float as[32 * 132];
    const int tid = threadIdx.x, tx = tid & 15, ty = tid >> 4;
    const int r0 = blockIdx.x * 32;
    for (int lin = tid; lin < 32 * 32; lin += 256) {
        int p = lin >> 5, k0 = (lin & 31) << 2;
        *(float4*)&as[p * 132 + k0] = *(const float4*)&g_x[(r0 + p) * FF + k0];
    }
    __syncthreads();
    float acc[2][8];
#pragma unroll
    for (int u = 0; u < 2; u++)
#pragma unroll
        for (int v = 0; v < 8; v++) acc[u][v] = 0.0f;
#pragma unroll 4
    for (int k = 0; k < FF; k++) {
        float4 w0 = __ldg((const float4*)&w[(k << 7) + (tx << 3)]);
        float4 w1 = __ldg((const float4*)&w[(k << 7) + (tx << 3) + 4]);
        fma_row(acc[0], as[(ty * 2 + 0) * 132 + k], w0, w1);
        fma_row(acc[1], as[(ty * 2 + 1) * 132 + k], w0, w1);
    }
#pragma unroll
    for (int u = 0; u < 2; u++) {
        int row = r0 + ty * 2 + u;
        *(float4*)&g_f[row * FF + (tx << 3)]     = make_float4(acc[u][0], acc[u][1], acc[u][2], acc[u][3]);
        *(float4*)&g_f[row * FF + (tx << 3) + 4] = make_float4(acc[u][4], acc[u][5], acc[u][6], acc[u][7]);
    }
}

// ------------------------------------------------------------------
// cfconv: y[b,i,h] = sum_j W[b,i,j,h] * f[b,j,h]
// W is stored triangle-only; read row (min(i,j), max(i,j)) — symmetric
// accesses from paired CTAs hit the same L2 lines (read dedup).
// grid = b(32) * i-chunk(16, 8 rows each) * h-half(2); 128 threads.
// ------------------------------------------------------------------
__global__ __launch_bounds__(128) void cfconv_kernel()
{
    __shared__ float f_s[128 * 64];
    const int bx = blockIdx.x;
    const int b  = bx >> 5;
    const int ic = (bx >> 1) & 15;
    const int hh = bx & 1;
    const int tid = threadIdx.x;
    const int hg = tid & 15;        // 4 features
    const int iL = tid >> 4;        // 0..7

    for (int lin = tid; lin < 2048; lin += 128) {
        int j = lin >> 4, h0 = (lin & 15) << 2;
        *(float4*)&f_s[j * 64 + h0] =
            *(const float4*)&g_f[((b << 7) + j) * FF + (hh << 6) + h0];
    }
    __syncthreads();

    const int i = ic * 8 + iL;
    const int foff = (hh << 6) + (hg << 2);
    const size_t brow = (size_t)(b * NN);
    float4 acc = make_float4(0.f, 0.f, 0.f, 0.f);
#pragma unroll 8
    for (int j = 0; j < NN; j++) {
        int ii = min(i, j), jj = max(i, j);
        const float4* wp = (const float4*)(g_W + ((brow + ii) * (size_t)NN + jj) * FF + foff);
        float4 w  = __ldg(wp);
        float4 fv = *(const float4*)&f_s[j * 64 + (hg << 2)];
        acc.x = fmaf(w.x, fv.x, acc.x);
        acc.y = fmaf(w.y, fv.y, acc.y);
        acc.z = fmaf(w.z, fv.z, acc.z);
        acc.w = fmaf(w.w, fv.w, acc.w);
    }
    *(float4*)&g_y[((b << 7) + i) * FF + foff] = acc;
}

// ------------------------------------------------------------------
// update: x += ssp(y @ w_f2out + b1) @ w_out + b2
// ------------------------------------------------------------------
__global__ __launch_bounds__(256) void update_kernel(
    const float* __restrict__ w1, const float* __restrict__ b1,
    const float* __restrict__ w2, const float* __restrict__ b2)
{
    __shared__ float as[32 * 132];
    const int tid = threadIdx.x, tx = tid & 15, ty = tid >> 4;
    const int r0 = blockIdx.x * 32;
    for (int lin = tid; lin < 32 * 32; lin += 256) {
        int p = lin >> 5, k0 = (lin & 31) << 2;
        *(float4*)&as[p * 132 + k0] = *(const float4*)&g_y[(r0 + p) * FF + k0];
    }
    __syncthreads();

    float t[2][8];
#pragma unroll
    for (int u = 0; u < 2; u++)
#pragma unroll
        for (int v = 0; v < 8; v++) t[u][v] = __ldg(&b1[(tx << 3) + v]);
#pragma unroll 4
    for (int k = 0; k < FF; k++) {
        float4 w0 = __ldg((const float4*)&w1[(k << 7) + (tx << 3)]);
        float4 wb = __ldg((const float4*)&w1[(k << 7) + (tx << 3) + 4]);
        fma_row(t[0], as[(ty * 2 + 0) * 132 + k], w0, wb);
        fma_row(t[1], as[(ty * 2 + 1) * 132 + k], w0, wb);
    }
#pragma unroll
    for (int u = 0; u < 2; u++)
#pragma unroll
        for (int v = 0; v < 8; v++) t[u][v] = sspf(t[u][v]);

    __syncthreads();   // all threads done reading the y tile
#pragma unroll
    for (int u = 0; u < 2; u++)
#pragma unroll
        for (int v = 0; v < 8; v++) as[(ty * 2 + u) * 132 + (tx << 3) + v] = t[u][v];
    __syncthreads();

    float acc[2][8];
#pragma unroll
    for (int u = 0; u < 2; u++)
#pragma unroll
        for (int v = 0; v < 8; v++) acc[u][v] = __ldg(&b2[(tx << 3) + v]);
#pragma unroll 4
    for (int k = 0; k < FF; k++) {
        float4 w0 = __ldg((const float4*)&w2[(k << 7) + (tx << 3)]);
        float4 wb = __ldg((const float4*)&w2[(k << 7) + (tx << 3) + 4]);
        fma_row(acc[0], as[(ty * 2 + 0) * 132 + k], w0, wb);
        fma_row(acc[1], as[(ty * 2 + 1) * 132 + k], w0, wb);
    }
    // residual update (vectorized read-modify-write)
#pragma unroll
    for (int u = 0; u < 2; u++) {
        int row = r0 + ty * 2 + u;
        float4* xp = (float4*)&g_x[row * FF + (tx << 3)];
        float4 x0 = xp[0], x1 = xp[1];
        x0.x += acc[u][0]; x0.y += acc[u][1]; x0.z += acc[u][2]; x0.w += acc[u][3];
        x1.x += acc[u][4]; x1.y += acc[u][5]; x1.z += acc[u][6]; x1.w += acc[u][7];
        xp[0] = x0; xp[1] = x1;
    }
}

// ------------------------------------------------------------------
// readout: out[n] = ssp(x @ w_aw1 + b_aw1) @ w_aw2 + b_aw2
// ------------------------------------------------------------------
__global__ __launch_bounds__(256) void readout_kernel(
    const float* __restrict__ w1, const float* __restrict__ b1,
    const float* __restrict__ w2, const float* __restrict__ b2,
    float* __restrict__ out)
{
    __shared__ float as[32 * 132];
    const int tid = threadIdx.x, tx = tid & 15, ty = tid >> 4;
    const int r0 = blockIdx.x * 32;
    for (int lin = tid; lin < 32 * 32; lin += 256) {
        int p = lin >> 5, k0 = (lin & 31) << 2;
        *(float4*)&as[p * 132 + k0] = *(const float4*)&g_x[(r0 + p) * FF + k0];
    }
    __syncthreads();

    float t[2][8];
#pragma unroll
    for (int u = 0; u < 2; u++)
#pragma unroll
        for (int v = 0; v < 8; v++) t[u][v] = __ldg(&b1[(tx << 3) + v]);
#pragma unroll 4
    for (int k = 0; k < FF; k++) {
        float4 w0 = __ldg((const float4*)&w1[(k << 7) + (tx << 3)]);
        float4 wb = __ldg((const float4*)&w1[(k << 7) + (tx << 3) + 4]);
        fma_row(t[0], as[(ty * 2 + 0) * 132 + k], w0, wb);
        fma_row(t[1], as[(ty * 2 + 1) * 132 + k], w0, wb);
    }

    float partial[2] = {0.0f, 0.0f};
#pragma unroll
    for (int u = 0; u < 2; u++)
#pragma unroll
        for (int v = 0; v < 8; v++)
            partial[u] += sspf(t[u][v]) * __ldg(&w2[(tx << 3) + v]);

    // reduce across the 16 tx lanes
#pragma unroll
    for (int off = 8; off >= 1; off >>= 1) {
        partial[0] += __shfl_xor_sync(0xffffffffu, partial[0], off, 16);
        partial[1] += __shfl_xor_sync(0xffffffffu, partial[1], off, 16);
    }
    if (tx == 0) {
        float bias = __ldg(&b2[0]);
        out[r0 + ty * 2 + 0] = partial[0] + bias;
        out[r0 + ty * 2 + 1] = partial[1] + bias;
    }
}

// ------------------------------------------------------------------
extern "C" void kernel_launch(void* const* d_in, const int* in_sizes, int n_in,
                              void* d_out, int out_size) {
    const int*   z      = (const int*)  d_in[0];
    const float* r      = (const float*)d_in[1];
    const float* emb    = (const float*)d_in[2];
    const float* w_in2f = (const float*)d_in[3];
    const float* w_f1   = (const float*)d_in[4];
    const float* b_f1   = (const float*)d_in[5];
    const float* w_f2   = (const float*)d_in[6];
    const float* b_f2   = (const float*)d_in[7];
    const float* w_f2o  = (const float*)d_in[8];
    const float* b_f2o  = (const float*)d_in[9];
    const float* w_out  = (const float*)d_in[10];
    const float* b_out  = (const float*)d_in[11];
    const float* w_aw1  = (const float*)d_in[12];
    const float* b_aw1  = (const float*)d_in[13];
    const float* w_aw2  = (const float*)d_in[14];
    const float* b_aw2  = (const float*)d_in[15];
    float* out = (float*)d_out;

    embed_kernel<<<(NROW * FF) / 256, 256>>>(z, emb);
    filter_kernel<<<BB * NTRI, 128>>>(r, w_f1, b_f1, w_f2, b_f2);

    for (int it = 0; it < 3; it++) {
        f_kernel<<<NROW / 32, 256>>>(w_in2f);
        cfconv_kernel<<<32 * 16 * 2, 128>>>();
        update_kernel<<<NROW / 32, 256>>>(w_f2o, b_f2o, w_out, b_out);
    }

    readout_kernel<<<NROW / 32, 256>>>(w_aw1, b_aw1, w_aw2, b_aw2, out);
}

// round 10
// speedup vs baseline: 1.6380x; 1.6380x over previous
#include <cuda_runtime.h>
#include <math.h>

// Problem constants
#define BB 32
#define NN 128
#define FF 128
#define GG 300
#define NPAIR (BB*NN*NN)     // 524288 pairs
#define NROW  (BB*NN)        // 4096 atom rows
#define KC 12                // rbf K-chunk (300 = 25*12)
#define NCHUNK 25
#define NTILE 16             // 128/8 row-tiles per batch
#define NTRI  (NTILE*(NTILE+1)/2)   // 136 upper-triangle tile pairs
#define NK 16384             // distance-table knots
#define DRANGE 40.0f         // table covers d in [0, 40)
#define LOG2F_ 0.69314718055994530942f

typedef unsigned long long u64;

// Scratch: device globals (no runtime allocation allowed)
// g_W holds only rows (i,j) with (i>>3) <= (j>>3)  (tile-level upper triangle).
static __device__ float g_W[(size_t)NPAIR * FF];  // 256 MiB filter matrix
static __device__ float g_T[(size_t)NK * FF];     // 8 MiB distance->W table
static __device__ float g_x[NROW * FF];
static __device__ float g_f[NROW * FF];
static __device__ float g_y[NROW * FF];

// ---------------- packed f32x2 helpers (Blackwell FFMA2) ----------------
__device__ __forceinline__ u64 pack2(float lo, float hi) {
    u64 r;
    asm("mov.b64 %0, {%1, %2};" : "=l"(r) : "f"(lo), "f"(hi));
    return r;
}
__device__ __forceinline__ void unpack2(u64 v, float& lo, float& hi) {
    asm("mov.b64 {%0, %1}, %2;" : "=f"(lo), "=f"(hi) : "l"(v));
}
__device__ __forceinline__ u64 ffma2(u64 a, u64 b, u64 c) {
    u64 d;
    asm("fma.rn.f32x2 %0, %1, %2, %3;" : "=l"(d) : "l"(a), "l"(b), "l"(c));
    return d;
}

// shifted softplus: log(0.5*exp(x)+0.5) == softplus(x) - log(2)
__device__ __forceinline__ float sspf(float x) {
    if (x > 30.0f) return x - LOG2F_;
    return __logf(fmaf(0.5f, __expf(x), 0.5f));
}

__device__ __forceinline__ void fma_row(float acc[8], float a, float4 w0, float4 w1) {
    acc[0] = fmaf(a, w0.x, acc[0]); acc[1] = fmaf(a, w0.y, acc[1]);
    acc[2] = fmaf(a, w0.z, acc[2]); acc[3] = fmaf(a, w0.w, acc[3]);
    acc[4] = fmaf(a, w1.x, acc[4]); acc[5] = fmaf(a, w1.y, acc[5]);
    acc[6] = fmaf(a, w1.z, acc[6]); acc[7] = fmaf(a, w1.w, acc[7]);
}

// ------------------------------------------------------------------
// Embedding gather: x[b,n,:] = emb[z[b,n], :]
// ------------------------------------------------------------------
__global__ void embed_kernel(const int* __restrict__ z, const float* __restrict__ emb) {
    int idx = blockIdx.x * blockDim.x + threadIdx.x;  // exactly NROW*FF threads
    int row = idx >> 7;
    int f   = idx & 127;
    g_x[idx] = emb[(z[row] << 7) + f];
}

// ------------------------------------------------------------------
// Table build: T[t,:] = (ssp(rbf(t*dt) @ w_f1 + b_f1)) @ w_f2 + b_f2
// One CTA = 64 knots x 128 features, 128 threads.
// Thread (tx = tid&15, ty = tid>>4) owns knots {8ty..8ty+7} and
// features {4tx..4tx+3} U {64+4tx..64+4tx+3}  (conflict-free LDS phases).
// ------------------------------------------------------------------
__global__ __launch_bounds__(128, 2) void table_kernel(
    const float* __restrict__ wf1, const float* __restrict__ bf1,
    const float* __restrict__ wf2, const float* __restrict__ bf2)
{
    __shared__ float h1_s[64 * 132];      // [knot][feat], stride 132 (528B, 16B-mult)
    __shared__ float wf1_s[KC * 128];
    __shared__ float rbf_s[KC * 64];
    __shared__ float d_s[64];

    const int tid = threadIdx.x;
    const int tx = tid & 15;
    const int ty = tid >> 4;              // 0..7
    const int p0 = blockIdx.x << 6;       // first knot of this CTA
    const int fA = tx << 2;               // first feature group base
    const int fB = 64 + (tx << 2);        // second feature group base

    if (tid < 64) {
        d_s[tid] = (float)(p0 + tid) * (DRANGE / (float)NK);
    }

    // phase-1 accumulators (init with b_f1)
    u64 acc[8][4];
    {
        u64 b0 = pack2(__ldg(&bf1[fA]),     __ldg(&bf1[fA + 1]));
        u64 b1 = pack2(__ldg(&bf1[fA + 2]), __ldg(&bf1[fA + 3]));
        u64 b2 = pack2(__ldg(&bf1[fB]),     __ldg(&bf1[fB + 1]));
        u64 b3 = pack2(__ldg(&bf1[fB + 2]), __ldg(&bf1[fB + 3]));
#pragma unroll
        for (int p = 0; p < 8; p++) { acc[p][0]=b0; acc[p][1]=b1; acc[p][2]=b2; acc[p][3]=b3; }
    }
    __syncthreads();

    const float step = 30.0f / 299.0f;
    for (int c = 0; c < NCHUNK; c++) {
        const int g0 = c * KC;
        // stage w_f1 chunk: KC*128 floats = 384 float4 (3 iters)
        {
            const float4* src = (const float4*)(wf1 + g0 * FF);
            float4* dst = (float4*)wf1_s;
#pragma unroll
            for (int i = 0; i < 3; i++) dst[tid + i * 128] = __ldg(&src[tid + i * 128]);
        }
        // generate rbf chunk: exp(-10*(d - c_g)^2)   (768 elems, 6 iters)
#pragma unroll
        for (int i = 0; i < 6; i++) {
            int lin = tid + i * 128;
            int k = lin >> 6, p = lin & 63;
            float dd = d_s[p] - (float)(g0 + k) * step;
            rbf_s[lin] = __expf(-10.0f * dd * dd);
        }
        __syncthreads();
#pragma unroll
        for (int k = 0; k < KC; k++) {
            float4 w0 = *(const float4*)&wf1_s[(k << 7) + fA];
            float4 w1 = *(const float4*)&wf1_s[(k << 7) + fB];
            u64 pw0 = pack2(w0.x, w0.y), pw1 = pack2(w0.z, w0.w);
            u64 pw2 = pack2(w1.x, w1.y), pw3 = pack2(w1.z, w1.w);
            float4 aL = *(const float4*)&rbf_s[(k << 6) + (ty << 3)];
            float4 aH = *(const float4*)&rbf_s[(k << 6) + (ty << 3) + 4];
            float av[8] = {aL.x, aL.y, aL.z, aL.w, aH.x, aH.y, aH.z, aH.w};
#pragma unroll
            for (int p = 0; p < 8; p++) {
                u64 pa = pack2(av[p], av[p]);
                acc[p][0] = ffma2(pw0, pa, acc[p][0]);
                acc[p][1] = ffma2(pw1, pa, acc[p][1]);
                acc[p][2] = ffma2(pw2, pa, acc[p][2]);
                acc[p][3] = ffma2(pw3, pa, acc[p][3]);
            }
        }
        __syncthreads();
    }

    // ssp, write h1 knot-major into smem (conflict-free: banks tx*4..)
#pragma unroll
    for (int p = 0; p < 8; p++) {
        float v[8];
        unpack2(acc[p][0], v[0], v[1]);
        unpack2(acc[p][1], v[2], v[3]);
        unpack2(acc[p][2], v[4], v[5]);
        unpack2(acc[p][3], v[6], v[7]);
        float* row = &h1_s[((ty << 3) + p) * 132];
        *(float4*)&row[fA] = make_float4(sspf(v[0]), sspf(v[1]), sspf(v[2]), sspf(v[3]));
        *(float4*)&row[fB] = make_float4(sspf(v[4]), sspf(v[5]), sspf(v[6]), sspf(v[7]));
    }
    __syncthreads();

    // phase 2: h1 @ w_f2 + b_f2  (k vectorized by 4; w_f2 from L1)
    u64 acc2[8][4];
    {
        u64 b0 = pack2(__ldg(&bf2[fA]),     __ldg(&bf2[fA + 1]));
        u64 b1 = pack2(__ldg(&bf2[fA + 2]), __ldg(&bf2[fA + 3]));
        u64 b2 = pack2(__ldg(&bf2[fB]),     __ldg(&bf2[fB + 1]));
        u64 b3 = pack2(__ldg(&bf2[fB + 2]), __ldg(&bf2[fB + 3]));
#pragma unroll
        for (int p = 0; p < 8; p++) { acc2[p][0]=b0; acc2[p][1]=b1; acc2[p][2]=b2; acc2[p][3]=b3; }
    }

    for (int k0 = 0; k0 < FF; k0 += 4) {
        u64 pw[4][4];
#pragma unroll
        for (int kk = 0; kk < 4; kk++) {
            float4 wA = __ldg((const float4*)&wf2[((k0 + kk) << 7) + fA]);
            float4 wB = __ldg((const float4*)&wf2[((k0 + kk) << 7) + fB]);
            pw[kk][0] = pack2(wA.x, wA.y); pw[kk][1] = pack2(wA.z, wA.w);
            pw[kk][2] = pack2(wB.x, wB.y); pw[kk][3] = pack2(wB.z, wB.w);
        }
#pragma unroll
        for (int p = 0; p < 8; p++) {
            float4 a4 = *(const float4*)&h1_s[((ty << 3) + p) * 132 + k0];
            float av[4] = {a4.x, a4.y, a4.z, a4.w};
#pragma unroll
            for (int kk = 0; kk < 4; kk++) {
                u64 pa = pack2(av[kk], av[kk]);
                acc2[p][0] = ffma2(pw[kk][0], pa, acc2[p][0]);
                acc2[p][1] = ffma2(pw[kk][1], pa, acc2[p][1]);
                acc2[p][2] = ffma2(pw[kk][2], pa, acc2[p][2]);
                acc2[p][3] = ffma2(pw[kk][3], pa, acc2[p][3]);
            }
        }
    }

    // store table rows
#pragma unroll
    for (int p = 0; p < 8; p++) {
        float v[8];
        unpack2(acc2[p][0], v[0], v[1]);
        unpack2(acc2[p][1], v[2], v[3]);
        unpack2(acc2[p][2], v[4], v[5]);
        unpack2(acc2[p][3], v[6], v[7]);
        size_t row = (size_t)(p0 + (ty << 3) + p);
        *(float4*)(g_T + row * FF + fA) = make_float4(v[0], v[1], v[2], v[3]);
        *(float4*)(g_T + row * FF + fB) = make_float4(v[4], v[5], v[6], v[7]);
    }
}

// ------------------------------------------------------------------
// W interp: for each upper-triangle pair (i,j): d -> lerp rows of g_T.
// CTA = one 8x8 tile-pair (64 pairs), 256 threads = 8 warps x 8 pairs.
// Each warp handles 8 pairs; 32 lanes cover the 128 features (float4).
// ------------------------------------------------------------------
__global__ __launch_bounds__(256) void winterp_kernel(const float* __restrict__ r)
{
    // decode blockIdx -> (batch, upper-triangle tile pair)
    const int b = blockIdx.x / NTRI;
    int t = blockIdx.x - b * NTRI;
    int ti = 0;
    while (t >= NTILE - ti) { t -= NTILE - ti; ti++; }
    const int tj = ti + t;
    const int i0 = ti << 3;
    const int j0 = tj << 3;

    const int lane = threadIdx.x & 31;
    const int wp   = threadIdx.x >> 5;    // 0..7
    const float inv_dt = (float)NK / DRANGE;

#pragma unroll
    for (int p = 0; p < 8; p++) {
        int q = (wp << 3) + p;            // local pair 0..63
        int i = i0 + (q >> 3), j = j0 + (q & 7);
        const float* ri = r + (b * NN + i) * 3;
        const float* rj = r + (b * NN + j) * 3;
        float dx = ri[0] - rj[0], dy = ri[1] - rj[1], dz = ri[2] - rj[2];
        float d = sqrtf(dx * dx + dy * dy + dz * dz + 1e-12f);

        float tpos = d * inv_dt;
        int k = (int)tpos;
        k = (k > NK - 2) ? (NK - 2) : k;
        float frac = fminf(tpos - (float)k, 1.0f);

        const float4* ta = (const float4*)(g_T + (size_t)k * FF) + lane;
        const float4* tb = ta + (FF / 4);
        float4 va = __ldg(ta), vb = __ldg(tb);
        float4 o;
        o.x = fmaf(frac, vb.x - va.x, va.x);
        o.y = fmaf(frac, vb.y - va.y, va.y);
        o.z = fmaf(frac, vb.z - va.z, va.z);
        o.w = fmaf(frac, vb.w - va.w, va.w);

        size_t row = ((size_t)(b * NN + i) * NN + j) * FF;
        ((float4*)(g_W + row))[lane] = o;
    }
}

// ------------------------------------------------------------------
// f = x @ w_in2f  (no bias). 32 rows per CTA.
// ------------------------------------------------------------------
__global__ __launch_bounds__(256) void f_kernel(const float* __restrict__ w)
{
    __shared__ float as[32 * 132];
    const int tid = threadIdx.x, tx = tid & 15, ty = tid >> 4;
    const int r0 = blockIdx.x * 32;
    for (int lin = tid; lin < 32 * 32; lin += 256) {
        int p = lin >> 5, k0 = (lin & 31) << 2;
        *(float4*)&as[p * 132 + k0] = *(const float4*)&g_x[(r0 + p) * FF + k0];
    }
    __syncthreads();
    float acc[2][8];
#pragma unroll
    for (int u = 0; u < 2; u++)
#pragma unroll
        for (int v = 0; v < 8; v++) acc[u][v] = 0.0f;
#pragma unroll 4
    for (int k = 0; k < FF; k++) {
        float4 w0 = __ldg((const float4*)&w[(k << 7) + (tx << 3)]);
        float4 w1 = __ldg((const float4*)&w[(k << 7) + (tx << 3) + 4]);
        fma_row(acc[0], as[(ty * 2 + 0) * 132 + k], w0, w1);
        fma_row(acc[1], as[(ty * 2 + 1) * 132 + k], w0, w1);
    }
#pragma unroll
    for (int u = 0; u < 2; u++) {
        int row = r0 + ty * 2 + u;
        *(float4*)&g_f[row * FF + (tx << 3)]     = make_float4(acc[u][0], acc[u][1], acc[u][2], acc[u][3]);
        *(float4*)&g_f[row * FF + (tx << 3) + 4] = make_float4(acc[u][4], acc[u][5], acc[u][6], acc[u][7]);
    }
}

// ------------------------------------------------------------------
// cfconv: y[b,i,h] = sum_j W[b,i,j,h] * f[b,j,h]
// W stored triangle-only; read row (min(i,j), max(i,j)).
// grid = b(32) * i-chunk(16, 8 rows each) * h-half(2); 128 threads.
// ------------------------------------------------------------------
__global__ __launch_bounds__(128) void cfconv_kernel()
{
    __shared__ float f_s[128 * 64];
    const int bx = blockIdx.x;
    const int b  = bx >> 5;
    const int ic = (bx >> 1) & 15;
    const int hh = bx & 1;
    const int tid = threadIdx.x;
    const int hg = tid & 15;        // 4 features
    const int iL = tid >> 4;        // 0..7

    for (int lin = tid; lin < 2048; lin += 128) {
        int j = lin >> 4, h0 = (lin & 15) << 2;
        *(float4*)&f_s[j * 64 + h0] =
            *(const float4*)&g_f[((b << 7) + j) * FF + (hh << 6) + h0];
    }
    __syncthreads();

    const int i = ic * 8 + iL;
    const int foff = (hh << 6) + (hg << 2);
    const size_t brow = (size_t)(b * NN);
    float4 acc = make_float4(0.f, 0.f, 0.f, 0.f);
#pragma unroll 8
    for (int j = 0; j < NN; j++) {
        int ii = min(i, j), jj = max(i, j);
        const float4* wpn = (const float4*)(g_W + ((brow + ii) * (size_t)NN + jj) * FF + foff);
        float4 w  = __ldg(wpn);
        float4 fv = *(const float4*)&f_s[j * 64 + (hg << 2)];
        acc.x = fmaf(w.x, fv.x, acc.x);
        acc.y = fmaf(w.y, fv.y, acc.y);
        acc.z = fmaf(w.z, fv.z, acc.z);
        acc.w = fmaf(w.w, fv.w, acc.w);
    }
    *(float4*)&g_y[((b << 7) + i) * FF + foff] = acc;
}

// ------------------------------------------------------------------
// update: x += ssp(y @ w_f2out + b1) @ w_out + b2
// ------------------------------------------------------------------
__global__ __launch_bounds__(256) void update_kernel(
    const float* __restrict__ w1, const float* __restrict__ b1,
    const float* __restrict__ w2, const float* __restrict__ b2)
{
    __shared__ float as[32 * 132];
    const int tid = threadIdx.x, tx = tid & 15, ty = tid >> 4;
    const int r0 = blockIdx.x * 32;
    for (int lin = tid; lin < 32 * 32; lin += 256) {
        int p = lin >> 5, k0 = (lin & 31) << 2;
        *(float4*)&as[p * 132 + k0] = *(const float4*)&g_y[(r0 + p) * FF + k0];
    }
    __syncthreads();

    float t[2][8];
#pragma unroll
    for (int u = 0; u < 2; u++)
#pragma unroll
        for (int v = 0; v < 8; v++) t[u][v] = __ldg(&b1[(tx << 3) + v]);
#pragma unroll 4
    for (int k = 0; k < FF; k++) {
        float4 w0 = __ldg((const float4*)&w1[(k << 7) + (tx << 3)]);
        float4 wb = __ldg((const float4*)&w1[(k << 7) + (tx << 3) + 4]);
        fma_row(t[0], as[(ty * 2 + 0) * 132 + k], w0, wb);
        fma_row(t[1], as[(ty * 2 + 1) * 132 + k], w0, wb);
    }
#pragma unroll
    for (int u = 0; u < 2; u++)
#pragma unroll
        for (int v = 0; v < 8; v++) t[u][v] = sspf(t[u][v]);

    __syncthreads();   // all threads done reading the y tile
#pragma unroll
    for (int u = 0; u < 2; u++)
#pragma unroll
        for (int v = 0; v < 8; v++) as[(ty * 2 + u) * 132 + (tx << 3) + v] = t[u][v];
    __syncthreads();

    float acc[2][8];
#pragma unroll
    for (int u = 0; u < 2; u++)
#pragma unroll
        for (int v = 0; v < 8; v++) acc[u][v] = __ldg(&b2[(tx << 3) + v]);
#pragma unroll 4
    for (int k = 0; k < FF; k++) {
        float4 w0 = __ldg((const float4*)&w2[(k << 7) + (tx << 3)]);
        float4 wb = __ldg((const float4*)&w2[(k << 7) + (tx << 3) + 4]);
        fma_row(acc[0], as[(ty * 2 + 0) * 132 + k], w0, wb);
        fma_row(acc[1], as[(ty * 2 + 1) * 132 + k], w0, wb);
    }
    // residual update (vectorized read-modify-write)
#pragma unroll
    for (int u = 0; u < 2; u++) {
        int row = r0 + ty * 2 + u;
        float4* xp = (float4*)&g_x[row * FF + (tx << 3)];
        float4 x0 = xp[0], x1 = xp[1];
        x0.x += acc[u][0]; x0.y += acc[u][1]; x0.z += acc[u][2]; x0.w += acc[u][3];
        x1.x += acc[u][4]; x1.y += acc[u][5]; x1.z += acc[u][6]; x1.w += acc[u][7];
        xp[0] = x0; xp[1] = x1;
    }
}

// ------------------------------------------------------------------
// readout: out[n] = ssp(x @ w_aw1 + b_aw1) @ w_aw2 + b_aw2
// ------------------------------------------------------------------
__global__ __launch_bounds__(256) void readout_kernel(
    const float* __restrict__ w1, const float* __restrict__ b1,
    const float* __restrict__ w2, const float* __restrict__ b2,
    float* __restrict__ out)
{
    __shared__ float as[32 * 132];
    const int tid = threadIdx.x, tx = tid & 15, ty = tid >> 4;
    const int r0 = blockIdx.x * 32;
    for (int lin = tid; lin < 32 * 32; lin += 256) {
        int p = lin >> 5, k0 = (lin & 31) << 2;
        *(float4*)&as[p * 132 + k0] = *(const float4*)&g_x[(r0 + p) * FF + k0];
    }
    __syncthreads();

    float t[2][8];
#pragma unroll
    for (int u = 0; u < 2; u++)
#pragma unroll
        for (int v = 0; v < 8; v++) t[u][v] = __ldg(&b1[(tx << 3) + v]);
#pragma unroll 4
    for (int k = 0; k < FF; k++) {
        float4 w0 = __ldg((const float4*)&w1[(k << 7) + (tx << 3)]);
        float4 wb = __ldg((const float4*)&w1[(k << 7) + (tx << 3) + 4]);
        fma_row(t[0], as[(ty * 2 + 0) * 132 + k], w0, wb);
        fma_row(t[1], as[(ty * 2 + 1) * 132 + k], w0, wb);
    }

    float partial[2] = {0.0f, 0.0f};
#pragma unroll
    for (int u = 0; u < 2; u++)
#pragma unroll
        for (int v = 0; v < 8; v++)
            partial[u] += sspf(t[u][v]) * __ldg(&w2[(tx << 3) + v]);

    // reduce across the 16 tx lanes
#pragma unroll
    for (int off = 8; off >= 1; off >>= 1) {
        partial[0] += __shfl_xor_sync(0xffffffffu, partial[0], off, 16);
        partial[1] += __shfl_xor_sync(0xffffffffu, partial[1], off, 16);
    }
    if (tx == 0) {
        float bias = __ldg(&b2[0]);
        out[r0 + ty * 2 + 0] = partial[0] + bias;
        out[r0 + ty * 2 + 1] = partial[1] + bias;
    }
}

// ------------------------------------------------------------------
extern "C" void kernel_launch(void* const* d_in, const int* in_sizes, int n_in,
                              void* d_out, int out_size) {
    const int*   z      = (const int*)  d_in[0];
    const float* r      = (const float*)d_in[1];
    const float* emb    = (const float*)d_in[2];
    const float* w_in2f = (const float*)d_in[3];
    const float* w_f1   = (const float*)d_in[4];
    const float* b_f1   = (const float*)d_in[5];
    const float* w_f2   = (const float*)d_in[6];
    const float* b_f2   = (const float*)d_in[7];
    const float* w_f2o  = (const float*)d_in[8];
    const float* b_f2o  = (const float*)d_in[9];
    const float* w_out  = (const float*)d_in[10];
    const float* b_out  = (const float*)d_in[11];
    const float* w_aw1  = (const float*)d_in[12];
    const float* b_aw1  = (const float*)d_in[13];
    const float* w_aw2  = (const float*)d_in[14];
    const float* b_aw2  = (const float*)d_in[15];
    float* out = (float*)d_out;

    embed_kernel<<<(NROW * FF) / 256, 256>>>(z, emb);
    table_kernel<<<NK / 64, 128>>>(w_f1, b_f1, w_f2, b_f2);
    winterp_kernel<<<BB * NTRI, 256>>>(r);

    for (int it = 0; it < 3; it++) {
        f_kernel<<<NROW / 32, 256>>>(w_in2f);
        cfconv_kernel<<<32 * 16 * 2, 128>>>();
        update_kernel<<<NROW / 32, 256>>>(w_f2o, b_f2o, w_out, b_out);
    }

    readout_kernel<<<NROW / 32, 256>>>(w_aw1, b_aw1, w_aw2, b_aw2, out);
}

// round 14
// speedup vs baseline: 2.7155x; 1.6578x over previous
#include <cuda_runtime.h>
#include <math.h>

// Problem constants
#define BB 32
#define NN 128
#define FF 128
#define GG 300
#define NPAIR (BB*NN*NN)     // 524288 pairs
#define NROW  (BB*NN)        // 4096 atom rows
#define KC 12                // rbf K-chunk (300 = 25*12)
#define NCHUNK 25
#define NTILE 16             // 128/8 row-tiles per batch
#define NTRI  (NTILE*(NTILE+1)/2)   // 136 upper-triangle tile pairs
#define NK 8192              // distance-table knots
#define DRANGE 40.0f         // table covers d in [0, 40)
#define LOG2F_ 0.69314718055994530942f

typedef unsigned long long u64;

// Scratch: device globals (no runtime allocation allowed)
// g_W holds only rows (i,j) with (i>>3) <= (j>>3)  (tile-level upper triangle).
static __device__ float g_W[(size_t)NPAIR * FF];   // 256 MiB filter matrix
static __device__ float g_T[(size_t)NK * FF];      // 4 MiB distance->W table
static __device__ float g_x[NROW * FF];
static __device__ float g_f[NROW * FF];
static __device__ float g_y[NROW * FF];
static __device__ float g_yp[2][NROW * FF];        // cfconv j-chunk partials

// ---------------- packed f32x2 helpers (Blackwell FFMA2) ----------------
__device__ __forceinline__ u64 pack2(float lo, float hi) {
    u64 r;
    asm("mov.b64 %0, {%1, %2};" : "=l"(r) : "f"(lo), "f"(hi));
    return r;
}
__device__ __forceinline__ void unpack2(u64 v, float& lo, float& hi) {
    asm("mov.b64 {%0, %1}, %2;" : "=f"(lo), "=f"(hi) : "l"(v));
}
__device__ __forceinline__ u64 ffma2(u64 a, u64 b, u64 c) {
    u64 d;
    asm("fma.rn.f32x2 %0, %1, %2, %3;" : "=l"(d) : "l"(a), "l"(b), "l"(c));
    return d;
}

// shifted softplus: log(0.5*exp(x)+0.5) == softplus(x) - log(2)
__device__ __forceinline__ float sspf(float x) {
    if (x > 30.0f) return x - LOG2F_;
    return __logf(fmaf(0.5f, __expf(x), 0.5f));
}

// ------------------------------------------------------------------
// Embedding gather: x[b,n,:] = emb[z[b,n], :]
// ------------------------------------------------------------------
__global__ void embed_kernel(const int* __restrict__ z, const float* __restrict__ emb) {
    int idx = blockIdx.x * blockDim.x + threadIdx.x;  // exactly NROW*FF threads
    int row = idx >> 7;
    int f   = idx & 127;
    g_x[idx] = emb[(z[row] << 7) + f];
}

// ------------------------------------------------------------------
// Table build: T[t,:] = (ssp(rbf(t*dt) @ w_f1 + b_f1)) @ w_f2 + b_f2
// One CTA = 64 knots x 128 features, 128 threads.
// ------------------------------------------------------------------
__global__ __launch_bounds__(128, 2) void table_kernel(
    const float* __restrict__ wf1, const float* __restrict__ bf1,
    const float* __restrict__ wf2, const float* __restrict__ bf2)
{
    __shared__ float h1_s[64 * 132];
    __shared__ float wf1_s[KC * 128];
    __shared__ float rbf_s[KC * 64];
    __shared__ float d_s[64];

    const int tid = threadIdx.x;
    const int tx = tid & 15;
    const int ty = tid >> 4;              // 0..7
    const int p0 = blockIdx.x << 6;       // first knot of this CTA
    const int fA = tx << 2;
    const int fB = 64 + (tx << 2);

    if (tid < 64) {
        d_s[tid] = (float)(p0 + tid) * (DRANGE / (float)NK);
    }

    u64 acc[8][4];
    {
        u64 b0 = pack2(__ldg(&bf1[fA]),     __ldg(&bf1[fA + 1]));
        u64 b1 = pack2(__ldg(&bf1[fA + 2]), __ldg(&bf1[fA + 3]));
        u64 b2 = pack2(__ldg(&bf1[fB]),     __ldg(&bf1[fB + 1]));
        u64 b3 = pack2(__ldg(&bf1[fB + 2]), __ldg(&bf1[fB + 3]));
#pragma unroll
        for (int p = 0; p < 8; p++) { acc[p][0]=b0; acc[p][1]=b1; acc[p][2]=b2; acc[p][3]=b3; }
    }
    __syncthreads();

    const float step = 30.0f / 299.0f;
    for (int c = 0; c < NCHUNK; c++) {
        const int g0 = c * KC;
        {
            const float4* src = (const float4*)(wf1 + g0 * FF);
            float4* dst = (float4*)wf1_s;
#pragma unroll
            for (int i = 0; i < 3; i++) dst[tid + i * 128] = __ldg(&src[tid + i * 128]);
        }
#pragma unroll
        for (int i = 0; i < 6; i++) {
            int lin = tid + i * 128;
            int k = lin >> 6, p = lin & 63;
            float dd = d_s[p] - (float)(g0 + k) * step;
            rbf_s[lin] = __expf(-10.0f * dd * dd);
        }
        __syncthreads();
#pragma unroll
        for (int k = 0; k < KC; k++) {
            float4 w0 = *(const float4*)&wf1_s[(k << 7) + fA];
            float4 w1 = *(const float4*)&wf1_s[(k << 7) + fB];
            u64 pw0 = pack2(w0.x, w0.y), pw1 = pack2(w0.z, w0.w);
            u64 pw2 = pack2(w1.x, w1.y), pw3 = pack2(w1.z, w1.w);
            float4 aL = *(const float4*)&rbf_s[(k << 6) + (ty << 3)];
            float4 aH = *(const float4*)&rbf_s[(k << 6) + (ty << 3) + 4];
            float av[8] = {aL.x, aL.y, aL.z, aL.w, aH.x, aH.y, aH.z, aH.w};
#pragma unroll
            for (int p = 0; p < 8; p++) {
                u64 pa = pack2(av[p], av[p]);
                acc[p][0] = ffma2(pw0, pa, acc[p][0]);
                acc[p][1] = ffma2(pw1, pa, acc[p][1]);
                acc[p][2] = ffma2(pw2, pa, acc[p][2]);
                acc[p][3] = ffma2(pw3, pa, acc[p][3]);
            }
        }
        __syncthreads();
    }

#pragma unroll
    for (int p = 0; p < 8; p++) {
        float v[8];
        unpack2(acc[p][0], v[0], v[1]);
        unpack2(acc[p][1], v[2], v[3]);
        unpack2(acc[p][2], v[4], v[5]);
        unpack2(acc[p][3], v[6], v[7]);
        float* row = &h1_s[((ty << 3) + p) * 132];
        *(float4*)&row[fA] = make_float4(sspf(v[0]), sspf(v[1]), sspf(v[2]), sspf(v[3]));
        *(float4*)&row[fB] = make_float4(sspf(v[4]), sspf(v[5]), sspf(v[6]), sspf(v[7]));
    }
    __syncthreads();

    u64 acc2[8][4];
    {
        u64 b0 = pack2(__ldg(&bf2[fA]),     __ldg(&bf2[fA + 1]));
        u64 b1 = pack2(__ldg(&bf2[fA + 2]), __ldg(&bf2[fA + 3]));
        u64 b2 = pack2(__ldg(&bf2[fB]),     __ldg(&bf2[fB + 1]));
        u64 b3 = pack2(__ldg(&bf2[fB + 2]), __ldg(&bf2[fB + 3]));
#pragma unroll
        for (int p = 0; p < 8; p++) { acc2[p][0]=b0; acc2[p][1]=b1; acc2[p][2]=b2; acc2[p][3]=b3; }
    }

    for (int k0 = 0; k0 < FF; k0 += 4) {
        u64 pw[4][4];
#pragma unroll
        for (int kk = 0; kk < 4; kk++) {
            float4 wA = __ldg((const float4*)&wf2[((k0 + kk) << 7) + fA]);
            float4 wB = __ldg((const float4*)&wf2[((k0 + kk) << 7) + fB]);
            pw[kk][0] = pack2(wA.x, wA.y); pw[kk][1] = pack2(wA.z, wA.w);
            pw[kk][2] = pack2(wB.x, wB.y); pw[kk][3] = pack2(wB.z, wB.w);
        }
#pragma unroll
        for (int p = 0; p < 8; p++) {
            float4 a4 = *(const float4*)&h1_s[((ty << 3) + p) * 132 + k0];
            float av[4] = {a4.x, a4.y, a4.z, a4.w};
#pragma unroll
            for (int kk = 0; kk < 4; kk++) {
                u64 pa = pack2(av[kk], av[kk]);
                acc2[p][0] = ffma2(pw[kk][0], pa, acc2[p][0]);
                acc2[p][1] = ffma2(pw[kk][1], pa, acc2[p][1]);
                acc2[p][2] = ffma2(pw[kk][2], pa, acc2[p][2]);
                acc2[p][3] = ffma2(pw[kk][3], pa, acc2[p][3]);
            }
        }
    }

#pragma unroll
    for (int p = 0; p < 8; p++) {
        float v[8];
        unpack2(acc2[p][0], v[0], v[1]);
        unpack2(acc2[p][1], v[2], v[3]);
        unpack2(acc2[p][2], v[4], v[5]);
        unpack2(acc2[p][3], v[6], v[7]);
        size_t row = (size_t)(p0 + (ty << 3) + p);
        *(float4*)(g_T + row * FF + fA) = make_float4(v[0], v[1], v[2], v[3]);
        *(float4*)(g_T + row * FF + fB) = make_float4(v[4], v[5], v[6], v[7]);
    }
}

// ------------------------------------------------------------------
// W interp: for each upper-triangle pair (i,j): d -> lerp rows of g_T.
// ------------------------------------------------------------------
__global__ __launch_bounds__(256) void winterp_kernel(const float* __restrict__ r)
{
    const int b = blockIdx.x / NTRI;
    int t = blockIdx.x - b * NTRI;
    int ti = 0;
    while (t >= NTILE - ti) { t -= NTILE - ti; ti++; }
    const int tj = ti + t;
    const int i0 = ti << 3;
    const int j0 = tj << 3;

    const int lane = threadIdx.x & 31;
    const int wp   = threadIdx.x >> 5;    // 0..7
    const float inv_dt = (float)NK / DRANGE;

#pragma unroll
    for (int p = 0; p < 8; p++) {
        int q = (wp << 3) + p;            // local pair 0..63
        int i = i0 + (q >> 3), j = j0 + (q & 7);
        const float* ri = r + (b * NN + i) * 3;
        const float* rj = r + (b * NN + j) * 3;
        float dx = ri[0] - rj[0], dy = ri[1] - rj[1], dz = ri[2] - rj[2];
        float d = sqrtf(dx * dx + dy * dy + dz * dz + 1e-12f);

        float tpos = d * inv_dt;
        int k = (int)tpos;
        k = (k > NK - 2) ? (NK - 2) : k;
        float frac = fminf(tpos - (float)k, 1.0f);

        const float4* ta = (const float4*)(g_T + (size_t)k * FF) + lane;
        const float4* tb = ta + (FF / 4);
        float4 va = __ldg(ta), vb = __ldg(tb);
        float4 o;
        o.x = fmaf(frac, vb.x - va.x, va.x);
        o.y = fmaf(frac, vb.y - va.y, va.y);
        o.z = fmaf(frac, vb.z - va.z, va.z);
        o.w = fmaf(frac, vb.w - va.w, va.w);

        size_t row = ((size_t)(b * NN + i) * NN + j) * FF;
        ((float4*)(g_W + row))[lane] = o;
    }
}

// ------------------------------------------------------------------
// Generic small GEMM: out[r, half*64 + c] = act(in @ w + b)  (16 rows/CTA)
// w half staged in smem (32KB) -> k-loop runs from smem only.
// Template: BIAS add bias, SSP apply ssp, RESID accumulate into out,
//           SUM2 input = in + in2 (elementwise).
// block 128: tx = tid&7 (8 feats), ty = tid>>3 (16 rows, 1 each).
// grid = (NROW/16) * 2 halves = 512.
// ------------------------------------------------------------------
template<bool BIAS, bool SSP, bool RESID, bool SUM2>
__global__ __launch_bounds__(128) void gemm16_kernel(
    const float* __restrict__ in, const float* __restrict__ in2,
    const float* __restrict__ w, const float* __restrict__ bias,
    float* __restrict__ out)
{
    __shared__ float w_s[128 * 64];   // [k][64 cols of this half]
    __shared__ float x_s[16 * 132];

    const int tid = threadIdx.x;
    const int tx = tid & 7;
    const int ty = tid >> 3;          // 0..15
    const int half = blockIdx.x & 1;
    const int r0 = (blockIdx.x >> 1) << 4;

    // stage w half: 2048 float4
    {
        const float4* w4 = (const float4*)w;    // row stride 32 float4
        float4* ws4 = (float4*)w_s;             // row stride 16 float4
#pragma unroll
        for (int i = 0; i < 16; i++) {
            int f4 = tid + (i << 7);            // 0..2047
            int k = f4 >> 4, c = f4 & 15;
            ws4[f4] = __ldg(&w4[(k << 5) + (half << 4) + c]);
        }
    }
    // stage input tile (optionally sum of two partials)
#pragma unroll
    for (int it = 0; it < 4; it++) {
        int lin = tid + (it << 7);              // 0..511 float4
        int row = lin >> 5, k0 = (lin & 31) << 2;
        float4 v = *(const float4*)&in[(r0 + row) * FF + k0];
        if (SUM2) {
            float4 v2 = *(const float4*)&in2[(r0 + row) * FF + k0];
            v.x += v2.x; v.y += v2.y; v.z += v2.z; v.w += v2.w;
        }
        *(float4*)&x_s[row * 132 + k0] = v;
    }
    __syncthreads();

    float acc[8];
#pragma unroll
    for (int v = 0; v < 8; v++) acc[v] = 0.0f;

    const float4* ws4 = (const float4*)w_s;
#pragma unroll 4
    for (int k = 0; k < FF; k++) {
        float a = x_s[ty * 132 + k];
        float4 w0 = ws4[(k << 4) + (tx << 1)];
        float4 w1 = ws4[(k << 4) + (tx << 1) + 1];
        acc[0] = fmaf(a, w0.x, acc[0]); acc[1] = fmaf(a, w0.y, acc[1]);
        acc[2] = fmaf(a, w0.z, acc[2]); acc[3] = fmaf(a, w0.w, acc[3]);
        acc[4] = fmaf(a, w1.x, acc[4]); acc[5] = fmaf(a, w1.y, acc[5]);
        acc[6] = fmaf(a, w1.z, acc[6]); acc[7] = fmaf(a, w1.w, acc[7]);
    }

    const int col = (half << 6) + (tx << 3);
    if (BIAS) {
#pragma unroll
        for (int v = 0; v < 8; v++) acc[v] += __ldg(&bias[col + v]);
    }
    if (SSP) {
#pragma unroll
        for (int v = 0; v < 8; v++) acc[v] = sspf(acc[v]);
    }
    float* op = &out[(r0 + ty) * FF + col];
    if (RESID) {
        float4* o4 = (float4*)op;
        float4 a0 = o4[0], a1 = o4[1];
        a0.x += acc[0]; a0.y += acc[1]; a0.z += acc[2]; a0.w += acc[3];
        a1.x += acc[4]; a1.y += acc[5]; a1.z += acc[6]; a1.w += acc[7];
        o4[0] = a0; o4[1] = a1;
    } else {
        ((float4*)op)[0] = make_float4(acc[0], acc[1], acc[2], acc[3]);
        ((float4*)op)[1] = make_float4(acc[4], acc[5], acc[6], acc[7]);
    }
}

// ------------------------------------------------------------------
// cfconv (j-split): yp[jc][b,i,h] = sum_{j in chunk jc} W[...] * f[b,j,h]
// W stored triangle-only; read row (min(i,j), max(i,j)).
// grid = b(32) * ic(16) * hh(2) * jc(2) = 2048; 128 threads; smem 16KB.
// ------------------------------------------------------------------
__global__ __launch_bounds__(128) void cfconv_kernel()
{
    __shared__ float f_s[64 * 64];
    const int bx = blockIdx.x;
    const int b  = bx >> 6;
    const int ic = (bx >> 2) & 15;
    const int hh = (bx >> 1) & 1;
    const int jc = bx & 1;
    const int tid = threadIdx.x;
    const int hg = tid & 15;        // 4 features
    const int iL = tid >> 4;        // 0..7

    // stage f chunk: 64 j-rows x 64 feats = 1024 float4
#pragma unroll
    for (int it = 0; it < 8; it++) {
        int lin = tid + (it << 7);
        int j = lin >> 4, h0 = (lin & 15) << 2;
        *(float4*)&f_s[j * 64 + h0] =
            *(const float4*)&g_f[((b << 7) + (jc << 6) + j) * FF + (hh << 6) + h0];
    }
    __syncthreads();

    const int i = (ic << 3) + iL;
    const int foff = (hh << 6) + (hg << 2);
    const size_t brow = (size_t)(b * NN);
    float4 acc = make_float4(0.f, 0.f, 0.f, 0.f);
#pragma unroll 8
    for (int j = 0; j < 64; j++) {
        int jg = (jc << 6) + j;
        int ii = min(i, jg), jj = max(i, jg);
        const float4* wpn = (const float4*)(g_W + ((brow + ii) * (size_t)NN + jj) * FF + foff);
        float4 w  = __ldg(wpn);
        float4 fv = *(const float4*)&f_s[j * 64 + (hg << 2)];
        acc.x = fmaf(w.x, fv.x, acc.x);
        acc.y = fmaf(w.y, fv.y, acc.y);
        acc.z = fmaf(w.z, fv.z, acc.z);
        acc.w = fmaf(w.w, fv.w, acc.w);
    }
    *(float4*)&g_yp[jc][((b << 7) + i) * FF + foff] = acc;
}

// ------------------------------------------------------------------
// final dot: out[row] = sum_f t[row,f] * w2[f] + b2   (t in g_y)
// one warp per row; grid = NROW/4, block 128.
// ------------------------------------------------------------------
__global__ __launch_bounds__(128) void dot_kernel(
    const float* __restrict__ w2, const float* __restrict__ b2,
    float* __restrict__ out)
{
    const int lane = threadIdx.x & 31;
    const int row = (blockIdx.x << 2) + (threadIdx.x >> 5);
    const float4 tv = *(const float4*)&g_y[row * FF + (lane << 2)];
    const float4 wv = __ldg((const float4*)&w2[lane << 2]);
    float val = tv.x * wv.x + tv.y * wv.y + tv.z * wv.z + tv.w * wv.w;
#pragma unroll
    for (int off = 16; off >= 1; off >>= 1)
        val += __shfl_xor_sync(0xffffffffu, val, off);
    if (lane == 0) out[row] = val + __ldg(&b2[0]);
}

// ------------------------------------------------------------------
extern "C" void kernel_launch(void* const* d_in, const int* in_sizes, int n_in,
                              void* d_out, int out_size) {
    const int*   z      = (const int*)  d_in[0];
    const float* r      = (const float*)d_in[1];
    const float* emb    = (const float*)d_in[2];
    const float* w_in2f = (const float*)d_in[3];
    const float* w_f1   = (const float*)d_in[4];
    const float* b_f1   = (const float*)d_in[5];
    const float* w_f2   = (const float*)d_in[6];
    const float* b_f2   = (const float*)d_in[7];
    const float* w_f2o  = (const float*)d_in[8];
    const float* b_f2o  = (const float*)d_in[9];
    const float* w_out  = (const float*)d_in[10];
    const float* b_out  = (const float*)d_in[11];
    const float* w_aw1  = (const float*)d_in[12];
    const float* b_aw1  = (const float*)d_in[13];
    const float* w_aw2  = (const float*)d_in[14];
    const float* b_aw2  = (const float*)d_in[15];
    float* out = (float*)d_out;

    float* gx = nullptr; float* gf = nullptr; float* gy = nullptr;
    float* gyp0 = nullptr; float* gyp1 = nullptr;
    cudaGetSymbolAddress((void**)&gx,  g_x);
    cudaGetSymbolAddress((void**)&gf,  g_f);
    cudaGetSymbolAddress((void**)&gy,  g_y);
    cudaGetSymbolAddress((void**)&gyp0, g_yp);
    gyp1 = gyp0 + NROW * FF;

    embed_kernel<<<(NROW * FF) / 256, 256>>>(z, emb);
    table_kernel<<<NK / 64, 128>>>(w_f1, b_f1, w_f2, b_f2);
    winterp_kernel<<<BB * NTRI, 256>>>(r);

    for (int it = 0; it < 3; it++) {
        // f = x @ w_in2f
        gemm16_kernel<false,false,false,false><<<(NROW/16)*2, 128>>>(gx, nullptr, w_in2f, nullptr, gf);
        // yp[0,1] = partial cfconv sums
        cfconv_kernel<<<32 * 16 * 2 * 2, 128>>>();
        // t = ssp((yp0+yp1) @ w_f2o + b_f2o)
        gemm16_kernel<true,true,false,true><<<(NROW/16)*2, 128>>>(gyp0, gyp1, w_f2o, b_f2o, gy);
        // x += t @ w_out + b_out
        gemm16_kernel<true,false,true,false><<<(NROW/16)*2, 128>>>(gy, nullptr, w_out, b_out, gx);
    }

    // t = ssp(x @ w_aw1 + b_aw1)
    gemm16_kernel<true,true,false,false><<<(NROW/16)*2, 128>>>(gx, nullptr, w_aw1, b_aw1, gy);
    // out = t . w_aw2 + b_aw2
    dot_kernel<<<NROW / 4, 128>>>(w_aw2, b_aw2, out);
}

// round 16
// speedup vs baseline: 3.4342x; 1.2647x over previous
#include <cuda_runtime.h>
#include <math.h>

// Problem constants
#define BB 32
#define NN 128
#define FF 128
#define GG 300
#define NPAIR (BB*NN*NN)     // 524288 pairs
#define NROW  (BB*NN)        // 4096 atom rows
#define KC 12                // rbf K-chunk (300 = 25*12)
#define NCHUNK 25
#define NTILE 16             // 128/8 row-tiles per batch
#define NTRI  (NTILE*(NTILE+1)/2)   // 136 upper-triangle tile pairs
#define NK 4096              // distance-table knots
#define DRANGE 40.0f         // table covers d in [0, 40)
#define LOG2F_ 0.69314718055994530942f

typedef unsigned long long u64;

// Scratch: device globals (no runtime allocation allowed)
// g_W holds only rows (i,j) with (i>>3) <= (j>>3)  (tile-level upper triangle).
static __device__ float g_W[(size_t)NPAIR * FF];   // 256 MiB filter matrix
static __device__ float g_T[(size_t)NK * FF];      // 2 MiB distance->W table
static __device__ float g_x[NROW * FF];
static __device__ float g_f[NROW * FF];
static __device__ float g_y[NROW * FF];
static __device__ float g_yp[2][NROW * FF];        // cfconv j-chunk partials

// ---------------- packed f32x2 helpers (Blackwell FFMA2) ----------------
__device__ __forceinline__ u64 pack2(float lo, float hi) {
    u64 r;
    asm("mov.b64 %0, {%1, %2};" : "=l"(r) : "f"(lo), "f"(hi));
    return r;
}
__device__ __forceinline__ void unpack2(u64 v, float& lo, float& hi) {
    asm("mov.b64 {%0, %1}, %2;" : "=f"(lo), "=f"(hi) : "l"(v));
}
__device__ __forceinline__ u64 ffma2(u64 a, u64 b, u64 c) {
    u64 d;
    asm("fma.rn.f32x2 %0, %1, %2, %3;" : "=l"(d) : "l"(a), "l"(b), "l"(c));
    return d;
}

// shifted softplus: log(0.5*exp(x)+0.5) == softplus(x) - log(2)
__device__ __forceinline__ float sspf(float x) {
    if (x > 30.0f) return x - LOG2F_;
    return __logf(fmaf(0.5f, __expf(x), 0.5f));
}

// ------------------------------------------------------------------
// Embedding gather: x[b,n,:] = emb[z[b,n], :]
// ------------------------------------------------------------------
__global__ void embed_kernel(const int* __restrict__ z, const float* __restrict__ emb) {
    int idx = blockIdx.x * blockDim.x + threadIdx.x;  // exactly NROW*FF threads
    int row = idx >> 7;
    int f   = idx & 127;
    g_x[idx] = emb[(z[row] << 7) + f];
}

// ------------------------------------------------------------------
// Table build: T[t,:] = (ssp(rbf(t*dt) @ w_f1 + b_f1)) @ w_f2 + b_f2
// One CTA = 64 knots x 128 features, 128 threads.
// ------------------------------------------------------------------
__global__ __launch_bounds__(128, 2) void table_kernel(
    const float* __restrict__ wf1, const float* __restrict__ bf1,
    const float* __restrict__ wf2, const float* __restrict__ bf2)
{
    __shared__ float h1_s[64 * 132];
    __shared__ float wf1_s[KC * 128];
    __shared__ float rbf_s[KC * 64];
    __shared__ float d_s[64];

    const int tid = threadIdx.x;
    const int tx = tid & 15;
    const int ty = tid >> 4;              // 0..7
    const int p0 = blockIdx.x << 6;       // first knot of this CTA
    const int fA = tx << 2;
    const int fB = 64 + (tx << 2);

    if (tid < 64) {
        d_s[tid] = (float)(p0 + tid) * (DRANGE / (float)NK);
    }

    u64 acc[8][4];
    {
        u64 b0 = pack2(__ldg(&bf1[fA]),     __ldg(&bf1[fA + 1]));
        u64 b1 = pack2(__ldg(&bf1[fA + 2]), __ldg(&bf1[fA + 3]));
        u64 b2 = pack2(__ldg(&bf1[fB]),     __ldg(&bf1[fB + 1]));
        u64 b3 = pack2(__ldg(&bf1[fB + 2]), __ldg(&bf1[fB + 3]));
#pragma unroll
        for (int p = 0; p < 8; p++) { acc[p][0]=b0; acc[p][1]=b1; acc[p][2]=b2; acc[p][3]=b3; }
    }
    __syncthreads();

    const float step = 30.0f / 299.0f;
    for (int c = 0; c < NCHUNK; c++) {
        const int g0 = c * KC;
        {
            const float4* src = (const float4*)(wf1 + g0 * FF);
            float4* dst = (float4*)wf1_s;
#pragma unroll
            for (int i = 0; i < 3; i++) dst[tid + i * 128] = __ldg(&src[tid + i * 128]);
        }
#pragma unroll
        for (int i = 0; i < 6; i++) {
            int lin = tid + i * 128;
            int k = lin >> 6, p = lin & 63;
            float dd = d_s[p] - (float)(g0 + k) * step;
            rbf_s[lin] = __expf(-10.0f * dd * dd);
        }
        __syncthreads();
#pragma unroll
        for (int k = 0; k < KC; k++) {
            float4 w0 = *(const float4*)&wf1_s[(k << 7) + fA];
            float4 w1 = *(const float4*)&wf1_s[(k << 7) + fB];
            u64 pw0 = pack2(w0.x, w0.y), pw1 = pack2(w0.z, w0.w);
            u64 pw2 = pack2(w1.x, w1.y), pw3 = pack2(w1.z, w1.w);
            float4 aL = *(const float4*)&rbf_s[(k << 6) + (ty << 3)];
            float4 aH = *(const float4*)&rbf_s[(k << 6) + (ty << 3) + 4];
            float av[8] = {aL.x, aL.y, aL.z, aL.w, aH.x, aH.y, aH.z, aH.w};
#pragma unroll
            for (int p = 0; p < 8; p++) {
                u64 pa = pack2(av[p], av[p]);
                acc[p][0] = ffma2(pw0, pa, acc[p][0]);
                acc[p][1] = ffma2(pw1, pa, acc[p][1]);
                acc[p][2] = ffma2(pw2, pa, acc[p][2]);
                acc[p][3] = ffma2(pw3, pa, acc[p][3]);
            }
        }
        __syncthreads();
    }

#pragma unroll
    for (int p = 0; p < 8; p++) {
        float v[8];
        unpack2(acc[p][0], v[0], v[1]);
        unpack2(acc[p][1], v[2], v[3]);
        unpack2(acc[p][2], v[4], v[5]);
        unpack2(acc[p][3], v[6], v[7]);
        float* row = &h1_s[((ty << 3) + p) * 132];
        *(float4*)&row[fA] = make_float4(sspf(v[0]), sspf(v[1]), sspf(v[2]), sspf(v[3]));
        *(float4*)&row[fB] = make_float4(sspf(v[4]), sspf(v[5]), sspf(v[6]), sspf(v[7]));
    }
    __syncthreads();

    u64 acc2[8][4];
    {
        u64 b0 = pack2(__ldg(&bf2[fA]),     __ldg(&bf2[fA + 1]));
        u64 b1 = pack2(__ldg(&bf2[fA + 2]), __ldg(&bf2[fA + 3]));
        u64 b2 = pack2(__ldg(&bf2[fB]),     __ldg(&bf2[fB + 1]));
        u64 b3 = pack2(__ldg(&bf2[fB + 2]), __ldg(&bf2[fB + 3]));
#pragma unroll
        for (int p = 0; p < 8; p++) { acc2[p][0]=b0; acc2[p][1]=b1; acc2[p][2]=b2; acc2[p][3]=b3; }
    }

    for (int k0 = 0; k0 < FF; k0 += 4) {
        u64 pw[4][4];
#pragma unroll
        for (int kk = 0; kk < 4; kk++) {
            float4 wA = __ldg((const float4*)&wf2[((k0 + kk) << 7) + fA]);
            float4 wB = __ldg((const float4*)&wf2[((k0 + kk) << 7) + fB]);
            pw[kk][0] = pack2(wA.x, wA.y); pw[kk][1] = pack2(wA.z, wA.w);
            pw[kk][2] = pack2(wB.x, wB.y); pw[kk][3] = pack2(wB.z, wB.w);
        }
#pragma unroll
        for (int p = 0; p < 8; p++) {
            float4 a4 = *(const float4*)&h1_s[((ty << 3) + p) * 132 + k0];
            float av[4] = {a4.x, a4.y, a4.z, a4.w};
#pragma unroll
            for (int kk = 0; kk < 4; kk++) {
                u64 pa = pack2(av[kk], av[kk]);
                acc2[p][0] = ffma2(pw[kk][0], pa, acc2[p][0]);
                acc2[p][1] = ffma2(pw[kk][1], pa, acc2[p][1]);
                acc2[p][2] = ffma2(pw[kk][2], pa, acc2[p][2]);
                acc2[p][3] = ffma2(pw[kk][3], pa, acc2[p][3]);
            }
        }
    }

#pragma unroll
    for (int p = 0; p < 8; p++) {
        float v[8];
        unpack2(acc2[p][0], v[0], v[1]);
        unpack2(acc2[p][1], v[2], v[3]);
        unpack2(acc2[p][2], v[4], v[5]);
        unpack2(acc2[p][3], v[6], v[7]);
        size_t row = (size_t)(p0 + (ty << 3) + p);
        *(float4*)(g_T + row * FF + fA) = make_float4(v[0], v[1], v[2], v[3]);
        *(float4*)(g_T + row * FF + fB) = make_float4(v[4], v[5], v[6], v[7]);
    }
}

// ------------------------------------------------------------------
// W interp: for each upper-triangle pair (i,j): d -> lerp rows of g_T.
// ------------------------------------------------------------------
__global__ __launch_bounds__(256) void winterp_kernel(const float* __restrict__ r)
{
    const int b = blockIdx.x / NTRI;
    int t = blockIdx.x - b * NTRI;
    int ti = 0;
    while (t >= NTILE - ti) { t -= NTILE - ti; ti++; }
    const int tj = ti + t;
    const int i0 = ti << 3;
    const int j0 = tj << 3;

    const int lane = threadIdx.x & 31;
    const int wp   = threadIdx.x >> 5;    // 0..7
    const float inv_dt = (float)NK / DRANGE;

#pragma unroll
    for (int p = 0; p < 8; p++) {
        int q = (wp << 3) + p;            // local pair 0..63
        int i = i0 + (q >> 3), j = j0 + (q & 7);
        const float* ri = r + (b * NN + i) * 3;
        const float* rj = r + (b * NN + j) * 3;
        float dx = ri[0] - rj[0], dy = ri[1] - rj[1], dz = ri[2] - rj[2];
        float d = sqrtf(dx * dx + dy * dy + dz * dz + 1e-12f);

        float tpos = d * inv_dt;
        int k = (int)tpos;
        k = (k > NK - 2) ? (NK - 2) : k;
        float frac = fminf(tpos - (float)k, 1.0f);

        const float4* ta = (const float4*)(g_T + (size_t)k * FF) + lane;
        const float4* tb = ta + (FF / 4);
        float4 va = __ldg(ta), vb = __ldg(tb);
        float4 o;
        o.x = fmaf(frac, vb.x - va.x, va.x);
        o.y = fmaf(frac, vb.y - va.y, va.y);
        o.z = fmaf(frac, vb.z - va.z, va.z);
        o.w = fmaf(frac, vb.w - va.w, va.w);

        size_t row = ((size_t)(b * NN + i) * NN + j) * FF;
        ((float4*)(g_W + row))[lane] = o;
    }
}

// ------------------------------------------------------------------
// Generic small GEMM: out[r, quarter*32 + c] = act(in @ w + b)
// 16 rows x 32-col quarter per CTA; w quarter (16KB) staged in smem.
// Template: BIAS add bias, SSP apply ssp, RESID accumulate into out,
//           SUM2 input = in + in2 (elementwise).
// block 128: tx = tid&7 (4 cols each), ty = tid>>3 (16 rows, 1 each).
// grid = (NROW/16) * 4 quarters = 1024.
// ------------------------------------------------------------------
template<bool BIAS, bool SSP, bool RESID, bool SUM2>
__global__ __launch_bounds__(128) void gemm16_kernel(
    const float* __restrict__ in, const float* __restrict__ in2,
    const float* __restrict__ w, const float* __restrict__ bias,
    float* __restrict__ out)
{
    __shared__ float w_s[128 * 32];   // [k][32 cols of this quarter] 16KB
    __shared__ float x_s[16 * 132];   // 8.4KB

    const int tid = threadIdx.x;
    const int tx = tid & 7;
    const int ty = tid >> 3;          // 0..15
    const int q  = blockIdx.x & 3;
    const int r0 = (blockIdx.x >> 2) << 4;

    // stage w quarter: 1024 float4 (8 per thread)
    {
        const float4* w4 = (const float4*)w;    // row stride 32 float4
        float4* ws4 = (float4*)w_s;             // row stride 8 float4
#pragma unroll
        for (int i = 0; i < 8; i++) {
            int f4 = tid + (i << 7);            // 0..1023
            int k = f4 >> 3, c = f4 & 7;
            ws4[f4] = __ldg(&w4[(k << 5) + (q << 3) + c]);
        }
    }
    // stage input tile (optionally sum of two partials): 512 float4
#pragma unroll
    for (int it = 0; it < 4; it++) {
        int lin = tid + (it << 7);              // 0..511 float4
        int row = lin >> 5, k0 = (lin & 31) << 2;
        float4 v = *(const float4*)&in[(r0 + row) * FF + k0];
        if (SUM2) {
            float4 v2 = *(const float4*)&in2[(r0 + row) * FF + k0];
            v.x += v2.x; v.y += v2.y; v.z += v2.z; v.w += v2.w;
        }
        *(float4*)&x_s[row * 132 + k0] = v;
    }
    __syncthreads();

    float4 acc = make_float4(0.f, 0.f, 0.f, 0.f);
    const float4* ws4 = (const float4*)w_s;
    const float* xrow = &x_s[ty * 132];
#pragma unroll 8
    for (int k4 = 0; k4 < 32; k4++) {
        float4 xv = *(const float4*)&xrow[k4 << 2];
        float4 w0 = ws4[((k4 << 2) + 0) * 8 + tx];
        float4 w1 = ws4[((k4 << 2) + 1) * 8 + tx];
        float4 w2 = ws4[((k4 << 2) + 2) * 8 + tx];
        float4 w3 = ws4[((k4 << 2) + 3) * 8 + tx];
        acc.x = fmaf(xv.x, w0.x, acc.x); acc.y = fmaf(xv.x, w0.y, acc.y);
        acc.z = fmaf(xv.x, w0.z, acc.z); acc.w = fmaf(xv.x, w0.w, acc.w);
        acc.x = fmaf(xv.y, w1.x, acc.x); acc.y = fmaf(xv.y, w1.y, acc.y);
        acc.z = fmaf(xv.y, w1.z, acc.z); acc.w = fmaf(xv.y, w1.w, acc.w);
        acc.x = fmaf(xv.z, w2.x, acc.x); acc.y = fmaf(xv.z, w2.y, acc.y);
        acc.z = fmaf(xv.z, w2.z, acc.z); acc.w = fmaf(xv.z, w2.w, acc.w);
        acc.x = fmaf(xv.w, w3.x, acc.x); acc.y = fmaf(xv.w, w3.y, acc.y);
        acc.z = fmaf(xv.w, w3.z, acc.z); acc.w = fmaf(xv.w, w3.w, acc.w);
    }

    const int col = (q << 5) + (tx << 2);
    if (BIAS) {
        float4 bv = __ldg((const float4*)&bias[col]);
        acc.x += bv.x; acc.y += bv.y; acc.z += bv.z; acc.w += bv.w;
    }
    if (SSP) {
        acc.x = sspf(acc.x); acc.y = sspf(acc.y);
        acc.z = sspf(acc.z); acc.w = sspf(acc.w);
    }
    float4* op = (float4*)&out[(r0 + ty) * FF + col];
    if (RESID) {
        float4 a0 = op[0];
        a0.x += acc.x; a0.y += acc.y; a0.z += acc.z; a0.w += acc.w;
        op[0] = a0;
    } else {
        op[0] = acc;
    }
}

// ------------------------------------------------------------------
// cfconv (j-split): yp[jc][b,i,h] = sum_{j in chunk jc} W[...] * f[b,j,h]
// W stored triangle-only; read row (min(i,j), max(i,j)).
// grid = b(32) * ic(16) * hh(2) * jc(2) = 2048; 128 threads; smem 16KB.
// ------------------------------------------------------------------
__global__ __launch_bounds__(128) void cfconv_kernel()
{
    __shared__ float f_s[64 * 64];
    const int bx = blockIdx.x;
    const int b  = bx >> 6;
    const int ic = (bx >> 2) & 15;
    const int hh = (bx >> 1) & 1;
    const int jc = bx & 1;
    const int tid = threadIdx.x;
    const int hg = tid & 15;        // 4 features
    const int iL = tid >> 4;        // 0..7

    // stage f chunk: 64 j-rows x 64 feats = 1024 float4
#pragma unroll
    for (int it = 0; it < 8; it++) {
        int lin = tid + (it << 7);
        int j = lin >> 4, h0 = (lin & 15) << 2;
        *(float4*)&f_s[j * 64 + h0] =
            *(const float4*)&g_f[((b << 7) + (jc << 6) + j) * FF + (hh << 6) + h0];
    }
    __syncthreads();

    const int i = (ic << 3) + iL;
    const int foff = (hh << 6) + (hg << 2);
    const size_t brow = (size_t)(b * NN);
    float4 acc = make_float4(0.f, 0.f, 0.f, 0.f);
#pragma unroll 8
    for (int j = 0; j < 64; j++) {
        int jg = (jc << 6) + j;
        int ii = min(i, jg), jj = max(i, jg);
        const float4* wpn = (const float4*)(g_W + ((brow + ii) * (size_t)NN + jj) * FF + foff);
        float4 w  = __ldg(wpn);
        float4 fv = *(const float4*)&f_s[j * 64 + (hg << 2)];
        acc.x = fmaf(w.x, fv.x, acc.x);
        acc.y = fmaf(w.y, fv.y, acc.y);
        acc.z = fmaf(w.z, fv.z, acc.z);
        acc.w = fmaf(w.w, fv.w, acc.w);
    }
    *(float4*)&g_yp[jc][((b << 7) + i) * FF + foff] = acc;
}

// ------------------------------------------------------------------
// final dot: out[row] = sum_f t[row,f] * w2[f] + b2   (t in g_y)
// one warp per row; grid = NROW/4, block 128.
// ------------------------------------------------------------------
__global__ __launch_bounds__(128) void dot_kernel(
    const float* __restrict__ w2, const float* __restrict__ b2,
    float* __restrict__ out)
{
    const int lane = threadIdx.x & 31;
    const int row = (blockIdx.x << 2) + (threadIdx.x >> 5);
    const float4 tv = *(const float4*)&g_y[row * FF + (lane << 2)];
    const float4 wv = __ldg((const float4*)&w2[lane << 2]);
    float val = tv.x * wv.x + tv.y * wv.y + tv.z * wv.z + tv.w * wv.w;
#pragma unroll
    for (int off = 16; off >= 1; off >>= 1)
        val += __shfl_xor_sync(0xffffffffu, val, off);
    if (lane == 0) out[row] = val + __ldg(&b2[0]);
}

// ------------------------------------------------------------------
extern "C" void kernel_launch(void* const* d_in, const int* in_sizes, int n_in,
                              void* d_out, int out_size) {
    const int*   z      = (const int*)  d_in[0];
    const float* r      = (const float*)d_in[1];
    const float* emb    = (const float*)d_in[2];
    const float* w_in2f = (const float*)d_in[3];
    const float* w_f1   = (const float*)d_in[4];
    const float* b_f1   = (const float*)d_in[5];
    const float* w_f2   = (const float*)d_in[6];
    const float* b_f2   = (const float*)d_in[7];
    const float* w_f2o  = (const float*)d_in[8];
    const float* b_f2o  = (const float*)d_in[9];
    const float* w_out  = (const float*)d_in[10];
    const float* b_out  = (const float*)d_in[11];
    const float* w_aw1  = (const float*)d_in[12];
    const float* b_aw1  = (const float*)d_in[13];
    const float* w_aw2  = (const float*)d_in[14];
    const float* b_aw2  = (const float*)d_in[15];
    float* out = (float*)d_out;

    float* gx = nullptr; float* gf = nullptr; float* gy = nullptr;
    float* gyp0 = nullptr; float* gyp1 = nullptr;
    cudaGetSymbolAddress((void**)&gx,  g_x);
    cudaGetSymbolAddress((void**)&gf,  g_f);
    cudaGetSymbolAddress((void**)&gy,  g_y);
    cudaGetSymbolAddress((void**)&gyp0, g_yp);
    gyp1 = gyp0 + NROW * FF;

    embed_kernel<<<(NROW * FF) / 256, 256>>>(z, emb);
    table_kernel<<<NK / 64, 128>>>(w_f1, b_f1, w_f2, b_f2);
    winterp_kernel<<<BB * NTRI, 256>>>(r);

    for (int it = 0; it < 3; it++) {
        // f = x @ w_in2f
        gemm16_kernel<false,false,false,false><<<(NROW/16)*4, 128>>>(gx, nullptr, w_in2f, nullptr, gf);
        // yp[0,1] = partial cfconv sums
        cfconv_kernel<<<32 * 16 * 2 * 2, 128>>>();
        // t = ssp((yp0+yp1) @ w_f2o + b_f2o)
        gemm16_kernel<true,true,false,true><<<(NROW/16)*4, 128>>>(gyp0, gyp1, w_f2o, b_f2o, gy);
        // x += t @ w_out + b_out
        gemm16_kernel<true,false,true,false><<<(NROW/16)*4, 128>>>(gy, nullptr, w_out, b_out, gx);
    }

    // t = ssp(x @ w_aw1 + b_aw1)
    gemm16_kernel<true,true,false,false><<<(NROW/16)*4, 128>>>(gx, nullptr, w_aw1, b_aw1, gy);
    // out = t . w_aw2 + b_aw2
    dot_kernel<<<NROW / 4, 128>>>(w_aw2, b_aw2, out);
}